// round 5
// baseline (speedup 1.0000x reference)
#include <cuda_runtime.h>
#include <cuda_fp16.h>
#include <cstdint>

#define BATCH   16384
#define NF      768
#define FT      1024
#define NROWS   (2*BATCH)      // virtual rows: [0,16384)=stm, [16384,32768)=nstm
#define MAXI    128            // max stored nonzeros per row (mean 32)
#define NSL     8              // output slices
#define OSL     128            // outputs per slice
#define RB      18             // blocks per slice: 8*18 = 144 blocks = 1 wave
#define THREADS 640            // 20 warps: 1 warp per row, ~102-reg budget
#define WARPS   20
#define STRIDE  (RB * WARPS)   // 360 rows per slice-pass
#define NSLOT   16             // 8 slices x 2 perspectives
#define SMEM_W  ((NF + 1) * OSL * 2)       // 196,864 B fp16 W slice (+ zero dummy row)
#define SMEM_BYTES (SMEM_W + 256 * 4)      // + W_out table (2 persp x 128 outs)

// ---- scratch (device globals; no allocation) ----
__device__ uint16_t g_idx[(size_t)NROWS * MAXI];   // 8 MB compacted indices (padded to x8)
__device__ int      g_cnt[NROWS];
__device__ float    g_acc[NSLOT * BATCH];          // 1 MB deterministic partials

// ============================================================================
// Kernel 1: warp-per-row nonzero scan + compaction (ballot/popc).
// Pads each row's index list to a multiple of 8 with dummy index NF (=768),
// which maps to a zeroed smem row in the accum kernel -> no masking needed.
// ============================================================================
__global__ __launch_bounds__(256) void scan_kernel(const float* __restrict__ stm,
                                                   const float* __restrict__ nstm) {
    int gtid = blockIdx.x * 256 + threadIdx.x;
    int warp = gtid >> 5;
    int lane = gtid & 31;
    if (warp >= NROWS) return;

    const float* row = (warp < BATCH) ? (stm + (size_t)warp * NF)
                                      : (nstm + (size_t)(warp - BATCH) * NF);
    const float4* row4 = (const float4*)row;
    uint16_t* out = g_idx + (size_t)warp * MAXI;

    int base = 0;
    #pragma unroll
    for (int j = 0; j < 6; j++) {                    // 6 * 32 lanes * 4 floats = 768
        float4 v = __ldcs(row4 + lane + 32 * j);     // streaming: read-once data
        float vv[4] = {v.x, v.y, v.z, v.w};
        #pragma unroll
        for (int c = 0; c < 4; c++) {
            bool p = (vv[c] != 0.0f);                // board entries are exactly {0,1}
            unsigned m = __ballot_sync(0xffffffffu, p);
            if (p) {
                int pos = base + __popc(m & ((1u << lane) - 1u));
                if (pos < MAXI)
                    out[pos] = (uint16_t)(4 * (lane + 32 * j) + c);
            }
            base += __popc(m);
        }
    }
    int cnt = (base < MAXI) ? base : MAXI;
    int padded = (cnt + 7) & ~7;
    if (padded > MAXI) padded = MAXI;
    if (lane < padded - cnt) out[cnt + lane] = (uint16_t)NF;   // dummy -> zero row
    if (lane == 0) g_cnt[warp] = cnt;
}

// ============================================================================
// Kernel 2: sparse accumulate from fp16 smem-resident W slice + fused epilogue.
// Block = (slice s, rg). smem: W_ftT slice [769][128] __half (row 768 zeroed)
// + 256-float W_out table. 20 warps, 1 warp per row, lane l serves outputs
// {4l..4l+3} via one LDS.64 per active feature (conflict-free).
// SOFTWARE PIPELINED: next row's cnt + 48 indices prefetched during current
// row's gathers -> L2 latency off the critical path.
// ============================================================================
__global__ __launch_bounds__(THREADS, 1) void accum_kernel(const float* __restrict__ W_ft,
                                                           const float* __restrict__ b_ft,
                                                           const float* __restrict__ W_out) {
    extern __shared__ __half W_sm[];   // [(NF+1)][OSL] then float wc[2][128]

    const int s  = blockIdx.x / RB;
    const int rg = blockIdx.x % RB;
    const int obase = s * OSL;
    float* wc = (float*)((char*)W_sm + SMEM_W);

    // ---- load W slice, convert to fp16, transpose into smem ----
    for (int p = threadIdx.x; p < 64 * (NF / 4); p += THREADS) {
        int fq = p >> 6;                 // 0..191
        int op = (p & 63) << 1;          // even output 0..126
        float4 a = *(const float4*)(W_ft + (size_t)(obase + op)     * NF + 4 * fq);
        float4 b = *(const float4*)(W_ft + (size_t)(obase + op + 1) * NF + 4 * fq);
        __half2* dst = (__half2*)W_sm;
        int w0 = (4 * fq) * (OSL / 2) + (op >> 1);
        dst[w0            ] = __floats2half2_rn(a.x, b.x);
        dst[w0 + OSL / 2  ] = __floats2half2_rn(a.y, b.y);
        dst[w0 + OSL      ] = __floats2half2_rn(a.z, b.z);
        dst[w0 + 3*OSL / 2] = __floats2half2_rn(a.w, b.w);
    }
    if (threadIdx.x < OSL / 2)           // zero dummy row NF
        ((__half2*)W_sm)[NF * (OSL / 2) + threadIdx.x] = __floats2half2_rn(0.f, 0.f);
    if (threadIdx.x < 256)               // W_out table: [persp][out in slice]
        wc[threadIdx.x] = W_out[(threadIdx.x >> 7) * FT + obase + (threadIdx.x & 127)];
    __syncthreads();

    const int w    = threadIdx.x >> 5;
    const int lane = threadIdx.x & 31;
    const float4 bf = *(const float4*)(b_ft + obase + lane * 4);
    const char* Wl = (const char*)W_sm + lane * 8;   // lane base (bytes)
    const float* wcl = wc + lane * 4;

    // ---- pipelined row loop ----
    int R = rg * WARPS + w;
    int cnt = g_cnt[R];
    const uint4* ip4 = (const uint4*)(g_idx + (size_t)R * MAXI);
    uint4 u0 = ip4[0], u1 = ip4[1], u2 = ip4[2],
          u3 = ip4[3], u4 = ip4[4], u5 = ip4[5];

    while (true) {
        // prefetch next row (warp-uniform branch)
        const int Rn = R + STRIDE;
        const bool more = (Rn < NROWS);
        int cn = 0;
        uint4 n0, n1, n2, n3, n4, n5;
        if (more) {
            cn = g_cnt[Rn];
            const uint4* np = (const uint4*)(g_idx + (size_t)Rn * MAXI);
            n0 = np[0]; n1 = np[1]; n2 = np[2]; n3 = np[3]; n4 = np[4]; n5 = np[5];
        }

        __half2 z = __floats2half2_rn(0.f, 0.f);
        __half2 aa0 = z, aa1 = z, ba0 = z, ba1 = z;
        const int ng = (cnt + 7) >> 3;               // padded to x8 with dummies

        #define G1(IDX, A0, A1) { \
            uint2 v = *(const uint2*)(Wl + (int)(IDX) * (OSL * 2)); \
            A0 = __hadd2(A0, *(__half2*)&v.x); A1 = __hadd2(A1, *(__half2*)&v.y); }
        #define GRP(U) { \
            G1(U.x & 0xffffu, aa0, aa1)  G1(U.x >> 16, ba0, ba1) \
            G1(U.y & 0xffffu, aa0, aa1)  G1(U.y >> 16, ba0, ba1) \
            G1(U.z & 0xffffu, aa0, aa1)  G1(U.z >> 16, ba0, ba1) \
            G1(U.w & 0xffffu, aa0, aa1)  G1(U.w >> 16, ba0, ba1) }

        if (ng > 0) GRP(u0)
        if (ng > 1) GRP(u1)
        if (ng > 2) GRP(u2)
        if (ng > 3) GRP(u3)
        if (ng > 4) GRP(u4)
        if (ng > 5) GRP(u5)
        if (cnt > 48) {                               // rare tail (~0.2% of rows)
            const uint16_t* ip = (const uint16_t*)ip4;
            for (int k = 48; k < cnt; k++)
                G1(ip[k], aa0, aa1)
        }
        #undef GRP
        #undef G1

        float2 xa = __half22float2(aa0), xb = __half22float2(ba0);
        float2 ya = __half22float2(aa1), yb = __half22float2(ba1);
        float p0 = fminf(fmaxf(bf.x + xa.x + xb.x, 0.f), 1.f);
        float p1 = fminf(fmaxf(bf.y + xa.y + xb.y, 0.f), 1.f);
        float p2 = fminf(fmaxf(bf.z + ya.x + yb.x, 0.f), 1.f);
        float p3 = fminf(fmaxf(bf.w + ya.y + yb.y, 0.f), 1.f);
        const int pr = (R >= BATCH);
        const float4 wo = *(const float4*)(wcl + pr * 128);
        float contrib = p0*p0*wo.x + p1*p1*wo.y + p2*p2*wo.z + p3*p3*wo.w;

        #pragma unroll
        for (int off = 16; off; off >>= 1)
            contrib += __shfl_xor_sync(0xffffffffu, contrib, off);

        if (lane == 0)
            g_acc[(size_t)(s * 2 + pr) * BATCH + (R & (BATCH - 1))] = contrib;

        if (!more) break;
        R = Rn; cnt = cn;
        ip4 = (const uint4*)(g_idx + (size_t)Rn * MAXI);
        u0 = n0; u1 = n1; u2 = n2; u3 = n3; u4 = n4; u5 = n5;
    }
}

// ============================================================================
// Kernel 3: sum 16 deterministic partials, add b_out, sigmoid.
// ============================================================================
__global__ __launch_bounds__(256) void finalize_kernel(const float* __restrict__ b_out,
                                                       float* __restrict__ out) {
    int b = blockIdx.x * 256 + threadIdx.x;
    if (b >= BATCH) return;
    float x = b_out[0];
    #pragma unroll
    for (int sl = 0; sl < NSLOT; sl++)
        x += g_acc[(size_t)sl * BATCH + b];
    out[b] = 1.0f / (1.0f + expf(-x));
}

extern "C" void kernel_launch(void* const* d_in, const int* in_sizes, int n_in,
                              void* d_out, int out_size) {
    const float* stm   = (const float*)d_in[0];
    const float* nstm  = (const float*)d_in[1];
    const float* W_ft  = (const float*)d_in[2];
    const float* b_ft  = (const float*)d_in[3];
    const float* W_out = (const float*)d_in[4];
    const float* b_out = (const float*)d_in[5];
    float* out = (float*)d_out;

    cudaFuncSetAttribute(accum_kernel,
                         cudaFuncAttributeMaxDynamicSharedMemorySize, SMEM_BYTES);

    scan_kernel<<<NROWS / 8, 256>>>(stm, nstm);                            // 4096 blocks
    accum_kernel<<<NSL * RB, THREADS, SMEM_BYTES>>>(W_ft, b_ft, W_out);    // 144 blocks
    finalize_kernel<<<(BATCH + 255) / 256, 256>>>(b_out, out);
}

// round 6
// speedup vs baseline: 1.1039x; 1.1039x over previous
#include <cuda_runtime.h>
#include <cuda_fp16.h>
#include <cstdint>

#define BATCH   16384
#define NF      768
#define FT      1024
#define NROWS   (2*BATCH)      // virtual rows: [0,16384)=stm, [16384,32768)=nstm
#define MAXI    128            // max stored nonzeros per row (mean 32)
#define NSL     8              // output slices
#define OSL     128            // outputs per slice
#define RB      18             // blocks per slice: 8*18 = 144 blocks = 1 wave
#define THREADS 1024           // 32 warps: 1 warp per row
#define WARPS   32
#define STRIDE  (RB * WARPS)   // 576
#define NSLOT   16             // 8 slices x 2 perspectives
#define SMEM_W   ((NF + 1) * OSL * 2)        // 196,864 B fp16 W slice (+ zero dummy row)
#define SMEM_WC  (SMEM_W)                    // 256 floats W_out table
#define SMEM_STG (SMEM_W + 1024)             // 32 warps x 2 bufs x 128 B staging
#define SMEM_BYTES (SMEM_STG + WARPS * 256)  // 206,080 B

// ---- scratch (device globals; no allocation) ----
__device__ uint16_t g_idx[(size_t)NROWS * MAXI];   // 8 MB compacted indices (padded to x8)
__device__ int      g_cnt[NROWS];
__device__ float    g_acc[NSLOT * BATCH];          // 1 MB deterministic partials

__device__ __forceinline__ uint32_t smem_u32(const void* p) {
    uint32_t a;
    asm("{ .reg .u64 t; cvta.to.shared.u64 t, %1; cvt.u32.u64 %0, t; }" : "=r"(a) : "l"(p));
    return a;
}
#define CP_ASYNC16(d, s) asm volatile("cp.async.cg.shared.global [%0], [%1], 16;" :: "r"(d), "l"(s) : "memory")
#define CP_COMMIT()      asm volatile("cp.async.commit_group;" ::: "memory")
#define CP_WAIT1()       asm volatile("cp.async.wait_group 1;" ::: "memory")
#define CP_WAIT0()       asm volatile("cp.async.wait_group 0;" ::: "memory")

// ============================================================================
// Kernel 1: warp-per-row nonzero scan + compaction (ballot/popc).
// Pads each row's index list to a multiple of 8 with dummy index NF (=768),
// which maps to a zeroed smem row in the accum kernel -> no masking needed.
// ============================================================================
__global__ __launch_bounds__(256) void scan_kernel(const float* __restrict__ stm,
                                                   const float* __restrict__ nstm) {
    int gtid = blockIdx.x * 256 + threadIdx.x;
    int warp = gtid >> 5;
    int lane = gtid & 31;
    if (warp >= NROWS) return;

    const float* row = (warp < BATCH) ? (stm + (size_t)warp * NF)
                                      : (nstm + (size_t)(warp - BATCH) * NF);
    const float4* row4 = (const float4*)row;
    uint16_t* out = g_idx + (size_t)warp * MAXI;

    int base = 0;
    #pragma unroll
    for (int j = 0; j < 6; j++) {                    // 6 * 32 lanes * 4 floats = 768
        float4 v = row4[lane + 32 * j];
        float vv[4] = {v.x, v.y, v.z, v.w};
        #pragma unroll
        for (int c = 0; c < 4; c++) {
            bool p = (vv[c] != 0.0f);                // board entries are exactly {0,1}
            unsigned m = __ballot_sync(0xffffffffu, p);
            if (p) {
                int pos = base + __popc(m & ((1u << lane) - 1u));
                if (pos < MAXI)
                    out[pos] = (uint16_t)(4 * (lane + 32 * j) + c);
            }
            base += __popc(m);
        }
    }
    int cnt = (base < MAXI) ? base : MAXI;
    int padded = (cnt + 7) & ~7;
    if (padded > MAXI) padded = MAXI;
    if (lane < padded - cnt) out[cnt + lane] = (uint16_t)NF;   // dummy -> zero row
    if (lane == 0) g_cnt[warp] = cnt;
}

// ============================================================================
// Kernel 2: sparse accumulate from fp16 smem-resident W slice + fused epilogue.
// 32 warps, 1 warp/row, lane l serves outputs {4l..4l+3} via LDS.64 gathers.
// Next row's 48 indices are staged into a per-warp smem double buffer with
// cp.async (zero register cost) while current row computes; g_cnt prefetched
// into one scalar. W_out constants come from a smem table.
// ============================================================================
__global__ __launch_bounds__(THREADS, 1) void accum_kernel(const float* __restrict__ W_ft,
                                                           const float* __restrict__ b_ft,
                                                           const float* __restrict__ W_out) {
    extern __shared__ __half W_sm[];   // [(NF+1)][OSL] | wc[2][128] | stage[32][2][128B]

    const int s  = blockIdx.x / RB;
    const int rg = blockIdx.x % RB;
    const int obase = s * OSL;
    float* wc = (float*)((char*)W_sm + SMEM_WC);

    // ---- load W slice, convert to fp16, transpose into smem ----
    for (int p = threadIdx.x; p < 64 * (NF / 4); p += THREADS) {
        int fq = p >> 6;                 // 0..191
        int op = (p & 63) << 1;          // even output 0..126
        float4 a = *(const float4*)(W_ft + (size_t)(obase + op)     * NF + 4 * fq);
        float4 b = *(const float4*)(W_ft + (size_t)(obase + op + 1) * NF + 4 * fq);
        __half2* dst = (__half2*)W_sm;
        int w0 = (4 * fq) * (OSL / 2) + (op >> 1);
        dst[w0            ] = __floats2half2_rn(a.x, b.x);
        dst[w0 + OSL / 2  ] = __floats2half2_rn(a.y, b.y);
        dst[w0 + OSL      ] = __floats2half2_rn(a.z, b.z);
        dst[w0 + 3*OSL / 2] = __floats2half2_rn(a.w, b.w);
    }
    if (threadIdx.x < OSL / 2)           // zero dummy row NF
        ((__half2*)W_sm)[NF * (OSL / 2) + threadIdx.x] = __floats2half2_rn(0.f, 0.f);
    if (threadIdx.x < 256)               // W_out table: [persp][out in slice]
        wc[threadIdx.x] = W_out[(threadIdx.x >> 7) * FT + obase + (threadIdx.x & 127)];
    __syncthreads();

    const int w    = threadIdx.x >> 5;
    const int lane = threadIdx.x & 31;
    const float4 bf = *(const float4*)(b_ft + obase + lane * 4);
    const char* Wl = (const char*)W_sm + lane * 8;   // lane gather base (bytes)
    const float* wcl = wc + lane * 4;

    char* stg_gen = (char*)W_sm + SMEM_STG + w * 256;     // this warp's 2x128B staging
    const uint32_t stg = smem_u32(stg_gen);

    // ---- pipelined row loop (cp.async index staging, no register prefetch) ----
    int R = rg * WARPS + w;
    if (lane < 6)
        CP_ASYNC16(stg + lane * 16, (const char*)(g_idx + (size_t)R * MAXI) + lane * 16);
    CP_COMMIT();
    int cnt = g_cnt[R];
    int buf = 0;

    while (true) {
        const int Rn = R + STRIDE;
        const bool more = (Rn < NROWS);
        int cn = 0;
        if (more) {
            if (lane < 6)
                CP_ASYNC16(stg + (buf ^ 1) * 128 + lane * 16,
                           (const char*)(g_idx + (size_t)Rn * MAXI) + lane * 16);
            CP_COMMIT();
            cn = g_cnt[Rn];
            CP_WAIT1();
        } else {
            CP_WAIT0();
        }
        __syncwarp();

        const uint4* st = (const uint4*)(stg_gen + buf * 128);
        uint4 u0 = st[0], u1 = st[1], u2 = st[2], u3 = st[3], u4 = st[4], u5 = st[5];

        __half2 z = __floats2half2_rn(0.f, 0.f);
        __half2 aa0 = z, aa1 = z, ba0 = z, ba1 = z;
        const int ng = (cnt + 7) >> 3;               // padded to x8 with dummies

        #define G1(IDX, A0, A1) { \
            uint2 v = *(const uint2*)(Wl + (int)(IDX) * (OSL * 2)); \
            A0 = __hadd2(A0, *(__half2*)&v.x); A1 = __hadd2(A1, *(__half2*)&v.y); }
        #define GRP(U) { \
            G1(U.x & 0xffffu, aa0, aa1)  G1(U.x >> 16, ba0, ba1) \
            G1(U.y & 0xffffu, aa0, aa1)  G1(U.y >> 16, ba0, ba1) \
            G1(U.z & 0xffffu, aa0, aa1)  G1(U.z >> 16, ba0, ba1) \
            G1(U.w & 0xffffu, aa0, aa1)  G1(U.w >> 16, ba0, ba1) }

        if (ng > 0) GRP(u0)
        if (ng > 1) GRP(u1)
        if (ng > 2) GRP(u2)
        if (ng > 3) GRP(u3)
        if (ng > 4) GRP(u4)
        if (ng > 5) GRP(u5)
        if (cnt > 48) {                               // rare tail (~0.2% of rows)
            const uint16_t* ip = g_idx + (size_t)R * MAXI;
            for (int k = 48; k < cnt; k++)
                G1(ip[k], aa0, aa1)
        }
        #undef GRP
        #undef G1

        float2 xa = __half22float2(aa0), xb = __half22float2(ba0);
        float2 ya = __half22float2(aa1), yb = __half22float2(ba1);
        float p0 = fminf(fmaxf(bf.x + xa.x + xb.x, 0.f), 1.f);
        float p1 = fminf(fmaxf(bf.y + xa.y + xb.y, 0.f), 1.f);
        float p2 = fminf(fmaxf(bf.z + ya.x + yb.x, 0.f), 1.f);
        float p3 = fminf(fmaxf(bf.w + ya.y + yb.y, 0.f), 1.f);
        const int pr = (R >= BATCH);
        const float4 wo = *(const float4*)(wcl + pr * 128);
        float contrib = p0*p0*wo.x + p1*p1*wo.y + p2*p2*wo.z + p3*p3*wo.w;

        #pragma unroll
        for (int off = 16; off; off >>= 1)
            contrib += __shfl_xor_sync(0xffffffffu, contrib, off);

        if (lane == 0)
            g_acc[(size_t)(s * 2 + pr) * BATCH + (R & (BATCH - 1))] = contrib;

        if (!more) break;
        __syncwarp();            // reads of stage[buf] done before it is refilled
        R = Rn; cnt = cn; buf ^= 1;
    }
}

// ============================================================================
// Kernel 3: sum 16 deterministic partials, add b_out, sigmoid.
// ============================================================================
__global__ __launch_bounds__(256) void finalize_kernel(const float* __restrict__ b_out,
                                                       float* __restrict__ out) {
    int b = blockIdx.x * 256 + threadIdx.x;
    if (b >= BATCH) return;
    float x = b_out[0];
    #pragma unroll
    for (int sl = 0; sl < NSLOT; sl++)
        x += g_acc[(size_t)sl * BATCH + b];
    out[b] = 1.0f / (1.0f + expf(-x));
}

extern "C" void kernel_launch(void* const* d_in, const int* in_sizes, int n_in,
                              void* d_out, int out_size) {
    const float* stm   = (const float*)d_in[0];
    const float* nstm  = (const float*)d_in[1];
    const float* W_ft  = (const float*)d_in[2];
    const float* b_ft  = (const float*)d_in[3];
    const float* W_out = (const float*)d_in[4];
    const float* b_out = (const float*)d_in[5];
    float* out = (float*)d_out;

    cudaFuncSetAttribute(accum_kernel,
                         cudaFuncAttributeMaxDynamicSharedMemorySize, SMEM_BYTES);

    scan_kernel<<<NROWS / 8, 256>>>(stm, nstm);                            // 4096 blocks
    accum_kernel<<<NSL * RB, THREADS, SMEM_BYTES>>>(W_ft, b_ft, W_out);    // 144 blocks
    finalize_kernel<<<(BATCH + 255) / 256, 256>>>(b_out, out);
}

// round 7
// speedup vs baseline: 1.1634x; 1.0538x over previous
#include <cuda_runtime.h>
#include <cuda_fp16.h>
#include <cstdint>

#define BATCH   16384
#define NF      768
#define FT      1024
#define NROWS   (2*BATCH)      // virtual rows: [0,16384)=stm, [16384,32768)=nstm
#define MAXI    128            // max stored nonzeros per row (mean 32)
#define NSL     8              // output slices
#define OSL     128            // outputs per slice
#define RB      18             // blocks per slice: 8*18 = 144 blocks = 1 wave
#define THREADS 1024           // 32 warps: 1 warp per row
#define WARPS   32
#define STRIDE  (RB * WARPS)   // 576
#define NSLOT   16             // 8 slices x 2 perspectives
#define SMEM_W  ((NF + 1) * OSL * 2)       // 196,864 B fp16 W slice (+ zero dummy row)
#define SMEM_BYTES (SMEM_W + 256 * 4)      // + W_out table (2 persp x 128 outs)

// ---- scratch (device globals; no allocation) ----
__device__ uint16_t g_idx[(size_t)NROWS * MAXI];   // 8 MB compacted indices (padded to x4)
__device__ int      g_cnt[NROWS];                  // PADDED counts (multiple of 4)
__device__ float    g_acc[NSLOT * BATCH];          // 1 MB deterministic partials

// ============================================================================
// Kernel 1: warp-per-row scan, lane-local masks (no serial ballot chain).
// Lane l owns floats [24l, 24l+24): builds a 24-bit presence mask, warp
// exclusive-scan of popcounts, then emits its indices. Pads the list to a
// multiple of 4 with dummy index NF (=768 -> zero smem row in accum) and
// stores the PADDED count.
// ============================================================================
__global__ __launch_bounds__(256) void scan_kernel(const float* __restrict__ stm,
                                                   const float* __restrict__ nstm) {
    int gtid = blockIdx.x * 256 + threadIdx.x;
    int warp = gtid >> 5;
    int lane = gtid & 31;
    if (warp >= NROWS) return;

    const float* row = (warp < BATCH) ? (stm + (size_t)warp * NF)
                                      : (nstm + (size_t)(warp - BATCH) * NF);
    const float4* row4 = (const float4*)row;
    uint16_t* out = g_idx + (size_t)warp * MAXI;

    // lane-local 24-bit presence mask (6 independent float4 loads)
    unsigned mask = 0;
    #pragma unroll
    for (int j = 0; j < 6; j++) {
        float4 v = row4[lane * 6 + j];
        if (v.x != 0.0f) mask |= 1u << (4 * j + 0);
        if (v.y != 0.0f) mask |= 1u << (4 * j + 1);
        if (v.z != 0.0f) mask |= 1u << (4 * j + 2);
        if (v.w != 0.0f) mask |= 1u << (4 * j + 3);
    }
    int cl = __popc(mask);

    // warp inclusive scan -> exclusive offset + total
    int pre = cl;
    #pragma unroll
    for (int off = 1; off < 32; off <<= 1) {
        int n = __shfl_up_sync(0xffffffffu, pre, off);
        if (lane >= off) pre += n;
    }
    int excl  = pre - cl;
    int total = __shfl_sync(0xffffffffu, pre, 31);

    // emit this lane's indices (order across lanes is ascending; order is
    // irrelevant to the accumulate anyway)
    int basep = excl;
    while (mask) {
        int b = __ffs(mask) - 1;
        mask &= mask - 1;
        if (basep < MAXI) out[basep] = (uint16_t)(lane * 24 + b);
        basep++;
    }

    int cnt = (total < MAXI) ? total : MAXI;
    int padded = (cnt + 3) & ~3;
    if (padded > MAXI) padded = MAXI;
    if (lane < padded - cnt) out[cnt + lane] = (uint16_t)NF;   // dummy -> zero row
    if (lane == 0) g_cnt[warp] = padded;
}

// ============================================================================
// Kernel 2: sparse accumulate from fp16 smem-resident W slice + fused epilogue.
// R3 structure (the champion): 32 warps, 1 warp/row, lane l serves outputs
// {4l..4l+3} via LDS.64; 6x uint4 unconditional register prefetch of indices.
// Changes: x4 index groups (12 predicated blocks, padded counts from scan)
// and 8 half2 accumulators = 4 independent HADD2 chains.
// ============================================================================
__global__ __launch_bounds__(THREADS, 1) void accum_kernel(const float* __restrict__ W_ft,
                                                           const float* __restrict__ b_ft,
                                                           const float* __restrict__ W_out) {
    extern __shared__ __half W_sm[];   // [(NF+1)][OSL] then float wc[2][128]

    const int s  = blockIdx.x / RB;
    const int rg = blockIdx.x % RB;
    const int obase = s * OSL;
    float* wc = (float*)((char*)W_sm + SMEM_W);

    // ---- load W slice, convert to fp16, transpose into smem ----
    for (int p = threadIdx.x; p < 64 * (NF / 4); p += THREADS) {
        int fq = p >> 6;                 // 0..191
        int op = (p & 63) << 1;          // even output 0..126
        float4 a = *(const float4*)(W_ft + (size_t)(obase + op)     * NF + 4 * fq);
        float4 b = *(const float4*)(W_ft + (size_t)(obase + op + 1) * NF + 4 * fq);
        __half2* dst = (__half2*)W_sm;
        int w0 = (4 * fq) * (OSL / 2) + (op >> 1);
        dst[w0            ] = __floats2half2_rn(a.x, b.x);
        dst[w0 + OSL / 2  ] = __floats2half2_rn(a.y, b.y);
        dst[w0 + OSL      ] = __floats2half2_rn(a.z, b.z);
        dst[w0 + 3*OSL / 2] = __floats2half2_rn(a.w, b.w);
    }
    if (threadIdx.x < OSL / 2)           // zero dummy row NF
        ((__half2*)W_sm)[NF * (OSL / 2) + threadIdx.x] = __floats2half2_rn(0.f, 0.f);
    if (threadIdx.x < 256)               // W_out table: [persp][out in slice]
        wc[threadIdx.x] = W_out[(threadIdx.x >> 7) * FT + obase + (threadIdx.x & 127)];
    __syncthreads();

    const int w    = threadIdx.x >> 5;
    const int lane = threadIdx.x & 31;
    const float4 bf = *(const float4*)(b_ft + obase + lane * 4);
    const char* Wl = (const char*)W_sm + lane * 8;   // lane gather base (bytes)
    const float* wcl = wc + lane * 4;

    for (int R = rg * WARPS + w; R < NROWS; R += STRIDE) {
        const int cnt = g_cnt[R];                    // padded (multiple of 4)
        const uint4* ip4 = (const uint4*)(g_idx + (size_t)R * MAXI);

        // unconditional parallel prefetch of 48 indices
        uint4 u0 = ip4[0], u1 = ip4[1], u2 = ip4[2],
              u3 = ip4[3], u4 = ip4[4], u5 = ip4[5];

        __half2 z = __floats2half2_rn(0.f, 0.f);
        __half2 aa0 = z, aa1 = z, ba0 = z, ba1 = z;  // 4 independent chains
        __half2 ca0 = z, ca1 = z, da0 = z, da1 = z;
        const int ng = cnt >> 2;                     // groups of 4

        #define G1(IDX, A0, A1) { \
            uint2 v = *(const uint2*)(Wl + (int)(IDX) * (OSL * 2)); \
            A0 = __hadd2(A0, *(__half2*)&v.x); A1 = __hadd2(A1, *(__half2*)&v.y); }
        #define GRP4(LO, HI) { \
            G1(LO & 0xffffu, aa0, aa1)  G1(LO >> 16, ba0, ba1) \
            G1(HI & 0xffffu, ca0, ca1)  G1(HI >> 16, da0, da1) }

        if (ng >  0) GRP4(u0.x, u0.y)
        if (ng >  1) GRP4(u0.z, u0.w)
        if (ng >  2) GRP4(u1.x, u1.y)
        if (ng >  3) GRP4(u1.z, u1.w)
        if (ng >  4) GRP4(u2.x, u2.y)
        if (ng >  5) GRP4(u2.z, u2.w)
        if (ng >  6) GRP4(u3.x, u3.y)
        if (ng >  7) GRP4(u3.z, u3.w)
        if (ng >  8) GRP4(u4.x, u4.y)
        if (ng >  9) GRP4(u4.z, u4.w)
        if (ng > 10) GRP4(u5.x, u5.y)
        if (ng > 11) GRP4(u5.z, u5.w)
        if (cnt > 48) {                               // rare tail (~0.2% of rows)
            const uint16_t* ip = (const uint16_t*)ip4;
            for (int k = 48; k < cnt; k++)
                G1(ip[k], aa0, aa1)
        }
        #undef GRP4
        #undef G1

        float2 f0 = __half22float2(aa0), f1 = __half22float2(ba0);
        float2 f2 = __half22float2(ca0), f3 = __half22float2(da0);
        float2 g0 = __half22float2(aa1), g1 = __half22float2(ba1);
        float2 g2 = __half22float2(ca1), g3 = __half22float2(da1);
        float p0 = fminf(fmaxf(bf.x + (f0.x + f1.x) + (f2.x + f3.x), 0.f), 1.f);
        float p1 = fminf(fmaxf(bf.y + (f0.y + f1.y) + (f2.y + f3.y), 0.f), 1.f);
        float p2 = fminf(fmaxf(bf.z + (g0.x + g1.x) + (g2.x + g3.x), 0.f), 1.f);
        float p3 = fminf(fmaxf(bf.w + (g0.y + g1.y) + (g2.y + g3.y), 0.f), 1.f);
        const int pr = (R >= BATCH);
        const float4 wo = *(const float4*)(wcl + pr * 128);
        float contrib = p0*p0*wo.x + p1*p1*wo.y + p2*p2*wo.z + p3*p3*wo.w;

        #pragma unroll
        for (int off = 16; off; off >>= 1)
            contrib += __shfl_xor_sync(0xffffffffu, contrib, off);

        if (lane == 0)
            g_acc[(size_t)(s * 2 + pr) * BATCH + (R & (BATCH - 1))] = contrib;
    }
}

// ============================================================================
// Kernel 3: sum 16 deterministic partials, add b_out, sigmoid.
// ============================================================================
__global__ __launch_bounds__(256) void finalize_kernel(const float* __restrict__ b_out,
                                                       float* __restrict__ out) {
    int b = blockIdx.x * 256 + threadIdx.x;
    if (b >= BATCH) return;
    float x = b_out[0];
    #pragma unroll
    for (int sl = 0; sl < NSLOT; sl++)
        x += g_acc[(size_t)sl * BATCH + b];
    out[b] = 1.0f / (1.0f + expf(-x));
}

extern "C" void kernel_launch(void* const* d_in, const int* in_sizes, int n_in,
                              void* d_out, int out_size) {
    const float* stm   = (const float*)d_in[0];
    const float* nstm  = (const float*)d_in[1];
    const float* W_ft  = (const float*)d_in[2];
    const float* b_ft  = (const float*)d_in[3];
    const float* W_out = (const float*)d_in[4];
    const float* b_out = (const float*)d_in[5];
    float* out = (float*)d_out;

    cudaFuncSetAttribute(accum_kernel,
                         cudaFuncAttributeMaxDynamicSharedMemorySize, SMEM_BYTES);

    scan_kernel<<<NROWS / 8, 256>>>(stm, nstm);                            // 4096 blocks
    accum_kernel<<<NSL * RB, THREADS, SMEM_BYTES>>>(W_ft, b_ft, W_out);    // 144 blocks
    finalize_kernel<<<(BATCH + 255) / 256, 256>>>(b_out, out);
}